// round 7
// baseline (speedup 1.0000x reference)
#include <cuda_runtime.h>
#include <cuda_bf16.h>
#include <cstdint>

#define IN_DIM  128
#define OUT_DIM 64
#define MAXN    50176

typedef unsigned long long ull;

// Scratch (static device globals: allocation-free rule)
__device__ __align__(16) float g_h[MAXN * OUT_DIM];   // projected features
__device__ __align__(16) float g_ssrc[MAXN];
__device__ __align__(16) float g_stgt[MAXN];
__device__ __align__(16) float g_esum[MAXN];

// ---------------------------------------------------------------------------
// Kernel 1: h = X @ W^T  (X:[N,128], W:[64,128] K-major), plus per-node
// scores s_src = h.a[0:64], s_tgt = h.a[64:128].
// Retiled: 256 threads = 64 nodes x 4 output-groups (og = tid&3, 16 outs each).
// X streamed from gmem (L2-resident, 4x redundancy ~9us of L2 traffic);
// only W lives in smem (32KB -> higher occupancy than the 68KB R4 version).
// Math uses packed fp32x2 FFMA2 (fma.rn.f32x2) with operands loaded as
// v2.u64 pairs -> half the FMA issue count at full fp32 precision.
// ---------------------------------------------------------------------------
__global__ void __launch_bounds__(256)
gat_gemm_kernel(const float* __restrict__ X,
                const float* __restrict__ W,
                const float* __restrict__ a,
                float* __restrict__ h,
                float* __restrict__ ssrc,
                float* __restrict__ stgt,
                int N)
{
    __shared__ float sW[OUT_DIM * IN_DIM];   // 32 KB

    const int tid = threadIdx.x;

    // Stage W as float4
    const float4* W4 = (const float4*)W;
    float4* sW4 = (float4*)sW;
    #pragma unroll
    for (int i = tid; i < OUT_DIM * IN_DIM / 4; i += 256) sW4[i] = W4[i];
    __syncthreads();

    const int og   = tid & 3;                // output group 0..3
    const int nl   = tid >> 2;               // node within block (0..63)
    const int node = blockIdx.x * 64 + nl;
    const int ob   = og * 16;
    const bool real = (node < N);
    const int cnode = real ? node : (N - 1); // clamp: keep lanes active for shfl

    // smem byte address of this og's W slab
    uint32_t wbase;
    asm("{ .reg .u64 t; cvta.to.shared.u64 t, %1; cvt.u32.u64 %0, t; }"
        : "=r"(wbase) : "l"(&sW[ob * IN_DIM]));

    const float4* xg = (const float4*)(X + (size_t)cnode * IN_DIM);

    ull acc2[16];
    #pragma unroll
    for (int j = 0; j < 16; j++) acc2[j] = 0ull;

    #pragma unroll 4
    for (int k4 = 0; k4 < IN_DIM / 4; k4++) {
        ull xlo, xhi;
        asm("ld.global.nc.v2.u64 {%0,%1}, [%2];"
            : "=l"(xlo), "=l"(xhi) : "l"(xg + k4));
        #pragma unroll
        for (int j = 0; j < 16; j++) {
            ull wlo, whi;
            asm("ld.shared.v2.u64 {%0,%1}, [%2];"
                : "=l"(wlo), "=l"(whi)
                : "r"(wbase + (uint32_t)(j * IN_DIM * 4 + k4 * 16)));
            asm("fma.rn.f32x2 %0, %1, %2, %0;" : "+l"(acc2[j]) : "l"(xlo), "l"(wlo));
            asm("fma.rn.f32x2 %0, %1, %2, %0;" : "+l"(acc2[j]) : "l"(xhi), "l"(whi));
        }
    }

    // Horizontal add of the packed pairs
    float acc[16];
    #pragma unroll
    for (int j = 0; j < 16; j++) {
        float lo, hi;
        asm("mov.b64 {%0,%1}, %2;" : "=f"(lo), "=f"(hi) : "l"(acc2[j]));
        acc[j] = lo + hi;
    }

    // Partial score dots; reduce across the 4 og-lanes (adjacent in warp)
    float ps = 0.f, pt = 0.f;
    #pragma unroll
    for (int j = 0; j < 16; j++) {
        ps += acc[j] * __ldg(&a[ob + j]);
        pt += acc[j] * __ldg(&a[OUT_DIM + ob + j]);
    }
    ps += __shfl_xor_sync(0xffffffffu, ps, 1);
    ps += __shfl_xor_sync(0xffffffffu, ps, 2);
    pt += __shfl_xor_sync(0xffffffffu, pt, 1);
    pt += __shfl_xor_sync(0xffffffffu, pt, 2);

    if (real) {
        float4* hp = (float4*)&h[(size_t)node * OUT_DIM + ob];
        #pragma unroll
        for (int j = 0; j < 4; j++)
            hp[j] = make_float4(acc[4*j], acc[4*j+1], acc[4*j+2], acc[4*j+3]);
        if (og == 0) { ssrc[node] = ps; stgt[node] = pt; }
    }
}

// ---------------------------------------------------------------------------
// Kernel 2: single fused edge pass (edge_index is int32 on device).
// No max-subtraction (scores bounded: std ~3.3, max ~16, exp(16)~9e6 << fp32
// max; softmax ratio shift-invariant -> exact up to rounding). Unnormalized
// accumulation; divide by esum later. One edge per 16-lane group; only the
// group leader computes score+exp (MUFU rt=8), broadcast via shfl.
// ---------------------------------------------------------------------------
__global__ void gat_edge_kernel(const int* __restrict__ ei,
                                const float* __restrict__ h,
                                const float* __restrict__ ssrc,
                                const float* __restrict__ stgt,
                                float* __restrict__ acc,
                                float* __restrict__ esum,
                                int E)
{
    int g   = (blockIdx.x * blockDim.x + threadIdx.x) >> 4;  // edge id
    int sub = threadIdx.x & 15;
    if (g >= E) return;

    int src = ei[g];
    int tgt = ei[E + g];

    float w;
    if (sub == 0) {
        float e = ssrc[src] + stgt[tgt];
        e = (e > 0.f) ? e : 0.2f * e;       // leaky_relu(0.2)
        w = __expf(e);
        atomicAdd(&esum[tgt], w);
    }
    w = __shfl_sync(0xffffffffu, w, threadIdx.x & 16, 32);

    float4 hv = ((const float4*)h)[(size_t)src * 16 + sub];
    float4 v  = make_float4(hv.x * w, hv.y * w, hv.z * w, hv.w * w);
    float4* dst = ((float4*)acc) + (size_t)tgt * 16 + sub;
    asm volatile("red.global.add.v4.f32 [%0], {%1,%2,%3,%4};"
                 :: "l"(dst), "f"(v.x), "f"(v.y), "f"(v.z), "f"(v.w)
                 : "memory");
}

// ---------------------------------------------------------------------------
// Kernel 3: out[i] = elu(acc[i] / (esum[node] + 1e-10))
// ---------------------------------------------------------------------------
__global__ void gat_final_kernel(float* __restrict__ out,
                                 const float* __restrict__ esum,
                                 int total)
{
    int i = blockIdx.x * blockDim.x + threadIdx.x;
    if (i >= total) return;
    float denom = esum[i >> 6] + 1e-10f;
    float v = out[i] / denom;
    out[i] = (v > 0.f) ? v : expm1f(v);
}

extern "C" void kernel_launch(void* const* d_in, const int* in_sizes, int n_in,
                              void* d_out, int out_size)
{
    const float* X  = (const float*)d_in[0];
    const int*   ei = (const int*)d_in[1];
    const float* W  = (const float*)d_in[2];
    const float* a  = (const float*)d_in[3];
    float* out = (float*)d_out;

    const int N = in_sizes[0] / IN_DIM;
    const int E = in_sizes[1] / 2;

    float *h, *ssrc, *stgt, *esum;
    cudaGetSymbolAddress((void**)&h,    g_h);
    cudaGetSymbolAddress((void**)&ssrc, g_ssrc);
    cudaGetSymbolAddress((void**)&stgt, g_stgt);
    cudaGetSymbolAddress((void**)&esum, g_esum);

    // Zero accumulators (graph-capturable async memsets)
    cudaMemsetAsync(out,  0, (size_t)out_size * sizeof(float));
    cudaMemsetAsync(esum, 0, (size_t)N * sizeof(float));

    gat_gemm_kernel<<<(N + 63) / 64, 256>>>(X, W, a, h, ssrc, stgt, N);

    long long edge_threads = (long long)E * 16;
    int eblocks = (int)((edge_threads + 255) / 256);
    gat_edge_kernel<<<eblocks, 256>>>(ei, h, ssrc, stgt, out, esum, E);

    gat_final_kernel<<<(out_size + 255) / 256, 256>>>(out, esum, out_size);
}

// round 11
// speedup vs baseline: 1.0060x; 1.0060x over previous
#include <cuda_runtime.h>
#include <cuda_bf16.h>
#include <cstdint>

#define IN_DIM  128
#define OUT_DIM 64
#define MAXN    50176
#define ROWP    132          // padded smem row stride (floats): 132 mod 32 = 4

typedef unsigned long long ull;

// Scratch (static device globals: allocation-free rule)
__device__ __align__(16) float g_h[MAXN * OUT_DIM];   // projected features
__device__ __align__(16) float g_ssrc[MAXN];
__device__ __align__(16) float g_stgt[MAXN];
__device__ __align__(16) float g_esum[MAXN];

// ---------------------------------------------------------------------------
// Kernel 1: h = X @ W^T  (X:[N,128], W:[64,128] K-major), plus per-node
// scores s_src = h.a[0:64], s_tgt = h.a[64:128].
// Block tile: 64 nodes x 64 outs, 256 threads. Per-thread register tile:
// 2 nodes x 8 outs. Both X and W staged in padded smem (R6 lesson: no
// per-thread strided LDG in the inner loop). Math: packed fp32x2 FFMA2.
// Per k4-step: 10 LDS.128 + 32 FFMA2 = 42 issues per 256 FMAs.
// ---------------------------------------------------------------------------
__global__ void __launch_bounds__(256)
gat_gemm_kernel(const float* __restrict__ X,
                const float* __restrict__ W,
                const float* __restrict__ a,
                float* __restrict__ h,
                float* __restrict__ ssrc,
                float* __restrict__ stgt,
                int N)
{
    extern __shared__ float smem[];
    float* sX = smem;                 // [64][132]
    float* sW = smem + 64 * ROWP;     // [64][132]

    const int tid = threadIdx.x;
    const int nodeBase = blockIdx.x * 64;

    // Stage W [64][128] -> padded rows
    for (int i = tid; i < 64 * 32; i += 256) {
        int r = i >> 5, c = i & 31;
        *(float4*)&sW[r * ROWP + c * 4] = ((const float4*)W)[(size_t)r * 32 + c];
    }
    // Stage X tile [64][128] -> padded rows (coalesced; clamp OOB rows)
    for (int i = tid; i < 64 * 32; i += 256) {
        int r = i >> 5, c = i & 31;
        int n = nodeBase + r; if (n >= N) n = N - 1;
        *(float4*)&sX[r * ROWP + c * 4] = ((const float4*)X)[(size_t)n * 32 + c];
    }
    __syncthreads();

    const int outg = tid & 7;          // 0..7  -> outputs outg*8..+7
    const int ng   = tid >> 3;         // 0..31 -> local nodes ng*2, ng*2+1
    const int n0   = ng * 2;
    const int ob   = outg * 8;

    uint32_t xb, wb;
    asm("{ .reg .u64 t; cvta.to.shared.u64 t, %1; cvt.u32.u64 %0, t; }"
        : "=r"(xb) : "l"(&sX[n0 * ROWP]));
    asm("{ .reg .u64 t; cvta.to.shared.u64 t, %1; cvt.u32.u64 %0, t; }"
        : "=r"(wb) : "l"(&sW[ob * ROWP]));

    ull a0[8], a1[8];                  // acc2[node][out]
    #pragma unroll
    for (int j = 0; j < 8; j++) { a0[j] = 0ull; a1[j] = 0ull; }

    #pragma unroll 2
    for (int k4 = 0; k4 < IN_DIM / 4; k4++) {
        const uint32_t ko = (uint32_t)(k4 * 16);
        ull x0lo, x0hi, x1lo, x1hi;
        asm("ld.shared.v2.u64 {%0,%1}, [%2];"
            : "=l"(x0lo), "=l"(x0hi) : "r"(xb + ko));
        asm("ld.shared.v2.u64 {%0,%1}, [%2];"
            : "=l"(x1lo), "=l"(x1hi) : "r"(xb + ROWP * 4 + ko));
        #pragma unroll
        for (int j = 0; j < 8; j++) {
            ull wlo, whi;
            asm("ld.shared.v2.u64 {%0,%1}, [%2];"
                : "=l"(wlo), "=l"(whi)
                : "r"(wb + (uint32_t)(j * ROWP * 4) + ko));
            asm("fma.rn.f32x2 %0, %1, %2, %0;" : "+l"(a0[j]) : "l"(x0lo), "l"(wlo));
            asm("fma.rn.f32x2 %0, %1, %2, %0;" : "+l"(a0[j]) : "l"(x0hi), "l"(whi));
            asm("fma.rn.f32x2 %0, %1, %2, %0;" : "+l"(a1[j]) : "l"(x1lo), "l"(wlo));
            asm("fma.rn.f32x2 %0, %1, %2, %0;" : "+l"(a1[j]) : "l"(x1hi), "l"(whi));
        }
    }

    // Unpack packed pairs -> final fp32 accumulators
    float f0[8], f1[8];
    #pragma unroll
    for (int j = 0; j < 8; j++) {
        float lo, hi;
        asm("mov.b64 {%0,%1}, %2;" : "=f"(lo), "=f"(hi) : "l"(a0[j]));
        f0[j] = lo + hi;
        asm("mov.b64 {%0,%1}, %2;" : "=f"(lo), "=f"(hi) : "l"(a1[j]));
        f1[j] = lo + hi;
    }

    // Score partials; reduce across the 8 outg lanes (consecutive in warp)
    float ps0 = 0.f, pt0 = 0.f, ps1 = 0.f, pt1 = 0.f;
    #pragma unroll
    for (int j = 0; j < 8; j++) {
        float as = __ldg(&a[ob + j]);
        float at = __ldg(&a[OUT_DIM + ob + j]);
        ps0 += f0[j] * as;  pt0 += f0[j] * at;
        ps1 += f1[j] * as;  pt1 += f1[j] * at;
    }
    #pragma unroll
    for (int d = 1; d < 8; d <<= 1) {
        ps0 += __shfl_xor_sync(0xffffffffu, ps0, d);
        pt0 += __shfl_xor_sync(0xffffffffu, pt0, d);
        ps1 += __shfl_xor_sync(0xffffffffu, ps1, d);
        pt1 += __shfl_xor_sync(0xffffffffu, pt1, d);
    }

    const int node0 = nodeBase + n0;
    const int node1 = node0 + 1;
    if (node0 < N) {
        float4* hp = (float4*)&h[(size_t)node0 * OUT_DIM + ob];
        hp[0] = make_float4(f0[0], f0[1], f0[2], f0[3]);
        hp[1] = make_float4(f0[4], f0[5], f0[6], f0[7]);
        if (outg == 0) { ssrc[node0] = ps0; stgt[node0] = pt0; }
    }
    if (node1 < N) {
        float4* hp = (float4*)&h[(size_t)node1 * OUT_DIM + ob];
        hp[0] = make_float4(f1[0], f1[1], f1[2], f1[3]);
        hp[1] = make_float4(f1[4], f1[5], f1[6], f1[7]);
        if (outg == 0) { ssrc[node1] = ps1; stgt[node1] = pt1; }
    }
}

// ---------------------------------------------------------------------------
// Kernel 2: single fused edge pass (edge_index is int32 on device).
// No max-subtraction (scores bounded: std ~3.3, max ~16, exp(16)~9e6 << fp32
// max; softmax ratio shift-invariant -> exact up to rounding). Unnormalized
// accumulation; divide by esum later. One edge per 16-lane group; only the
// group leader computes score+exp (MUFU rt=8), broadcast via shfl.
// ---------------------------------------------------------------------------
__global__ void gat_edge_kernel(const int* __restrict__ ei,
                                const float* __restrict__ h,
                                const float* __restrict__ ssrc,
                                const float* __restrict__ stgt,
                                float* __restrict__ acc,
                                float* __restrict__ esum,
                                int E)
{
    int g   = (blockIdx.x * blockDim.x + threadIdx.x) >> 4;  // edge id
    int sub = threadIdx.x & 15;
    if (g >= E) return;

    int src = ei[g];
    int tgt = ei[E + g];

    float w;
    if (sub == 0) {
        float e = ssrc[src] + stgt[tgt];
        e = (e > 0.f) ? e : 0.2f * e;       // leaky_relu(0.2)
        w = __expf(e);
        atomicAdd(&esum[tgt], w);
    }
    w = __shfl_sync(0xffffffffu, w, threadIdx.x & 16, 32);

    float4 hv = ((const float4*)h)[(size_t)src * 16 + sub];
    float4 v  = make_float4(hv.x * w, hv.y * w, hv.z * w, hv.w * w);
    float4* dst = ((float4*)acc) + (size_t)tgt * 16 + sub;
    asm volatile("red.global.add.v4.f32 [%0], {%1,%2,%3,%4};"
                 :: "l"(dst), "f"(v.x), "f"(v.y), "f"(v.z), "f"(v.w)
                 : "memory");
}

// ---------------------------------------------------------------------------
// Kernel 3: out[i] = elu(acc[i] / (esum[node] + 1e-10))
// ---------------------------------------------------------------------------
__global__ void gat_final_kernel(float* __restrict__ out,
                                 const float* __restrict__ esum,
                                 int total)
{
    int i = blockIdx.x * blockDim.x + threadIdx.x;
    if (i >= total) return;
    float denom = esum[i >> 6] + 1e-10f;
    float v = out[i] / denom;
    out[i] = (v > 0.f) ? v : expm1f(v);
}

extern "C" void kernel_launch(void* const* d_in, const int* in_sizes, int n_in,
                              void* d_out, int out_size)
{
    const float* X  = (const float*)d_in[0];
    const int*   ei = (const int*)d_in[1];
    const float* W  = (const float*)d_in[2];
    const float* a  = (const float*)d_in[3];
    float* out = (float*)d_out;

    const int N = in_sizes[0] / IN_DIM;
    const int E = in_sizes[1] / 2;

    float *h, *ssrc, *stgt, *esum;
    cudaGetSymbolAddress((void**)&h,    g_h);
    cudaGetSymbolAddress((void**)&ssrc, g_ssrc);
    cudaGetSymbolAddress((void**)&stgt, g_stgt);
    cudaGetSymbolAddress((void**)&esum, g_esum);

    // Zero accumulators (graph-capturable async memsets)
    cudaMemsetAsync(out,  0, (size_t)out_size * sizeof(float));
    cudaMemsetAsync(esum, 0, (size_t)N * sizeof(float));

    const int SMEM_BYTES = 2 * 64 * ROWP * sizeof(float);   // 67584
    cudaFuncSetAttribute(gat_gemm_kernel,
                         cudaFuncAttributeMaxDynamicSharedMemorySize, SMEM_BYTES);

    gat_gemm_kernel<<<(N + 63) / 64, 256, SMEM_BYTES>>>(X, W, a, h, ssrc, stgt, N);

    long long edge_threads = (long long)E * 16;
    int eblocks = (int)((edge_threads + 255) / 256);
    gat_edge_kernel<<<eblocks, 256>>>(ei, h, ssrc, stgt, out, esum, E);

    gat_final_kernel<<<(out_size + 255) / 256, 256>>>(out, esum, out_size);
}

// round 15
// speedup vs baseline: 2.6275x; 2.6119x over previous
#include <cuda_runtime.h>
#include <cuda_bf16.h>
#include <cstdint>

#define IN_DIM  128
#define OUT_DIM 64
#define MAXN    50176
#define ROWP    132          // padded X row stride (floats): 132 mod 32 = 4

// Scratch (static device globals: allocation-free rule)
__device__ __align__(16) float g_h[MAXN * OUT_DIM];   // projected features
__device__ __align__(16) float g_ssrc[MAXN];
__device__ __align__(16) float g_stgt[MAXN];
__device__ __align__(16) float g_esum[MAXN];

// ---------------------------------------------------------------------------
// Kernel 1: h = X @ W^T  (X:[N,128], W:[64,128] K-major), plus per-node
// scores s_src = h.a[0:64], s_tgt = h.a[64:128].
// Block tile: 128 nodes x 64 outs, 256 threads.
// Warp layout = R4's proven one: og = tid>>6, so all 32 lanes of a warp share
// og -> every W load is a single-address BROADCAST (free on the crossbar).
// X rows padded to 132 floats (stride = 4 mod 32 banks) -> conflict-free.
// Each thread: 2 nodes (nl, nl+64) x 16 outs = 32 independent FMA chains;
// per k4-step: 18 LDS.128 + 128 FFMA (1.14 issues/FMA vs R4's 1.27).
// ---------------------------------------------------------------------------
__global__ void __launch_bounds__(256)
gat_gemm_kernel(const float* __restrict__ X,
                const float* __restrict__ W,
                const float* __restrict__ a,
                float* __restrict__ h,
                float* __restrict__ ssrc,
                float* __restrict__ stgt,
                int N)
{
    extern __shared__ float smem[];
    float* sW = smem;                     // [64][128]   8192 floats (unpadded: broadcast)
    float* sX = sW + OUT_DIM * IN_DIM;    // [128][132]  16896 floats
    float* sS = sX + 128 * ROWP;          // [4][128]    512
    float* sT = sS + 512;                 // [4][128]    512

    const int tid = threadIdx.x;
    const int nodeBase = blockIdx.x * 128;

    // Stage W [64][128] as float4 (coalesced)
    const float4* W4 = (const float4*)W;
    float4* sW4 = (float4*)sW;
    #pragma unroll
    for (int i = tid; i < OUT_DIM * IN_DIM / 4; i += 256) sW4[i] = W4[i];

    // Stage X tile [128][128] -> padded rows (coalesced; clamp OOB rows)
    for (int i = tid; i < 128 * 32; i += 256) {
        int r = i >> 5, c = i & 31;
        int n = nodeBase + r; if (n >= N) n = N - 1;
        *(float4*)&sX[r * ROWP + c * 4] = ((const float4*)X)[(size_t)n * 32 + c];
    }
    __syncthreads();

    const int nl = tid & 63;              // local node (second node = nl+64)
    const int og = tid >> 6;              // output group 0..3 (same across warp!)
    const int ob = og * 16;

    float acc0[16], acc1[16];
    #pragma unroll
    for (int j = 0; j < 16; j++) { acc0[j] = 0.f; acc1[j] = 0.f; }

    const float* x0r = &sX[nl * ROWP];
    const float* x1r = &sX[(nl + 64) * ROWP];

    #pragma unroll 2
    for (int k4 = 0; k4 < IN_DIM / 4; k4++) {
        float4 x0 = *(const float4*)&x0r[k4 * 4];
        float4 x1 = *(const float4*)&x1r[k4 * 4];
        #pragma unroll
        for (int j = 0; j < 16; j++) {
            float4 w = *(const float4*)&sW[(ob + j) * IN_DIM + k4 * 4];
            acc0[j] += x0.x * w.x + x0.y * w.y + x0.z * w.z + x0.w * w.w;
            acc1[j] += x1.x * w.x + x1.y * w.y + x1.z * w.z + x1.w * w.w;
        }
    }

    // Score partials over this thread's 16 outs, for both nodes
    float ps0 = 0.f, pt0 = 0.f, ps1 = 0.f, pt1 = 0.f;
    #pragma unroll
    for (int j = 0; j < 16; j++) {
        float as = __ldg(&a[ob + j]);
        float at = __ldg(&a[OUT_DIM + ob + j]);
        ps0 += acc0[j] * as;  pt0 += acc0[j] * at;
        ps1 += acc1[j] * as;  pt1 += acc1[j] * at;
    }
    sS[og * 128 + nl]      = ps0;
    sT[og * 128 + nl]      = pt0;
    sS[og * 128 + 64 + nl] = ps1;
    sT[og * 128 + 64 + nl] = pt1;

    const int node0 = nodeBase + nl;
    const int node1 = node0 + 64;
    if (node0 < N) {
        float4* hp = (float4*)&h[(size_t)node0 * OUT_DIM + ob];
        #pragma unroll
        for (int j = 0; j < 4; j++)
            hp[j] = make_float4(acc0[4*j], acc0[4*j+1], acc0[4*j+2], acc0[4*j+3]);
    }
    if (node1 < N) {
        float4* hp = (float4*)&h[(size_t)node1 * OUT_DIM + ob];
        #pragma unroll
        for (int j = 0; j < 4; j++)
            hp[j] = make_float4(acc1[4*j], acc1[4*j+1], acc1[4*j+2], acc1[4*j+3]);
    }
    __syncthreads();
    // Reduce the 4 og-partials; og==0 threads handle both of their nodes
    if (og == 0) {
        if (node0 < N) {
            ssrc[node0] = sS[nl] + sS[128 + nl] + sS[256 + nl] + sS[384 + nl];
            stgt[node0] = sT[nl] + sT[128 + nl] + sT[256 + nl] + sT[384 + nl];
        }
        if (node1 < N) {
            int q = 64 + nl;
            ssrc[node1] = sS[q] + sS[128 + q] + sS[256 + q] + sS[384 + q];
            stgt[node1] = sT[q] + sT[128 + q] + sT[256 + q] + sT[384 + q];
        }
    }
}

// ---------------------------------------------------------------------------
// Kernel 2: single fused edge pass (edge_index is int32 on device).
// No max-subtraction (scores bounded: std ~3.3, max ~16, exp(16)~9e6 << fp32
// max; softmax ratio shift-invariant -> exact up to rounding). Unnormalized
// accumulation; divide by esum later. One edge per 16-lane group; only the
// group leader computes score+exp (MUFU rt=8), broadcast via shfl.
// ---------------------------------------------------------------------------
__global__ void gat_edge_kernel(const int* __restrict__ ei,
                                const float* __restrict__ h,
                                const float* __restrict__ ssrc,
                                const float* __restrict__ stgt,
                                float* __restrict__ acc,
                                float* __restrict__ esum,
                                int E)
{
    int g   = (blockIdx.x * blockDim.x + threadIdx.x) >> 4;  // edge id
    int sub = threadIdx.x & 15;
    if (g >= E) return;

    int src = ei[g];
    int tgt = ei[E + g];

    float w;
    if (sub == 0) {
        float e = ssrc[src] + stgt[tgt];
        e = (e > 0.f) ? e : 0.2f * e;       // leaky_relu(0.2)
        w = __expf(e);
        atomicAdd(&esum[tgt], w);
    }
    w = __shfl_sync(0xffffffffu, w, threadIdx.x & 16, 32);

    float4 hv = ((const float4*)h)[(size_t)src * 16 + sub];
    float4 v  = make_float4(hv.x * w, hv.y * w, hv.z * w, hv.w * w);
    float4* dst = ((float4*)acc) + (size_t)tgt * 16 + sub;
    asm volatile("red.global.add.v4.f32 [%0], {%1,%2,%3,%4};"
                 :: "l"(dst), "f"(v.x), "f"(v.y), "f"(v.z), "f"(v.w)
                 : "memory");
}

// ---------------------------------------------------------------------------
// Kernel 3: out[i] = elu(acc[i] / (esum[node] + 1e-10))
// ---------------------------------------------------------------------------
__global__ void gat_final_kernel(float* __restrict__ out,
                                 const float* __restrict__ esum,
                                 int total)
{
    int i = blockIdx.x * blockDim.x + threadIdx.x;
    if (i >= total) return;
    float denom = esum[i >> 6] + 1e-10f;
    float v = out[i] / denom;
    out[i] = (v > 0.f) ? v : expm1f(v);
}

extern "C" void kernel_launch(void* const* d_in, const int* in_sizes, int n_in,
                              void* d_out, int out_size)
{
    const float* X  = (const float*)d_in[0];
    const int*   ei = (const int*)d_in[1];
    const float* W  = (const float*)d_in[2];
    const float* a  = (const float*)d_in[3];
    float* out = (float*)d_out;

    const int N = in_sizes[0] / IN_DIM;
    const int E = in_sizes[1] / 2;

    float *h, *ssrc, *stgt, *esum;
    cudaGetSymbolAddress((void**)&h,    g_h);
    cudaGetSymbolAddress((void**)&ssrc, g_ssrc);
    cudaGetSymbolAddress((void**)&stgt, g_stgt);
    cudaGetSymbolAddress((void**)&esum, g_esum);

    // Zero accumulators (graph-capturable async memsets)
    cudaMemsetAsync(out,  0, (size_t)out_size * sizeof(float));
    cudaMemsetAsync(esum, 0, (size_t)N * sizeof(float));

    // smem: W 8192 + X 16896 + sS 512 + sT 512 = 26112 floats = 104448 B
    const int SMEM_BYTES = 26112 * sizeof(float);
    cudaFuncSetAttribute(gat_gemm_kernel,
                         cudaFuncAttributeMaxDynamicSharedMemorySize, SMEM_BYTES);

    gat_gemm_kernel<<<(N + 127) / 128, 256, SMEM_BYTES>>>(X, W, a, h, ssrc, stgt, N);

    long long edge_threads = (long long)E * 16;
    int eblocks = (int)((edge_threads + 255) / 256);
    gat_edge_kernel<<<eblocks, 256>>>(ei, h, ssrc, stgt, out, esum, E);

    gat_final_kernel<<<(out_size + 255) / 256, 256>>>(out, esum, out_size);
}